// round 17
// baseline (speedup 1.0000x reference)
#include <cuda_runtime.h>

#define BATCH  16
#define SEQ    1024
#define HDIM   768
#define NHEADS 12
#define HD     64
#define MTOK   (BATCH*SEQ)      /* 16384 */
#define QKVN   (3*HDIM)         /* 2304  */

// ------------------------- device scratch (no alloc rule) -------------------
__device__ __align__(256) float g_Q[BATCH*NHEADS*SEQ*HD];
__device__ __align__(256) float g_K[BATCH*NHEADS*SEQ*HD];
__device__ __align__(256) float g_V[BATCH*NHEADS*SEQ*HD];
__device__ __align__(256) float g_AttO[MTOK*HDIM];

// Fast exp2 on (-inf, 0]: degree-6 poly + exponent bits. No MUFU.
__device__ __forceinline__ float exp2f_fast(float x) {
    x = fmaxf(x, -125.0f);
    float t = floorf(x);
    float f = x - t;
    float p = 1.5403530e-4f;
    p = fmaf(p, f, 1.3333558e-3f);
    p = fmaf(p, f, 9.6181291e-3f);
    p = fmaf(p, f, 5.5504109e-2f);
    p = fmaf(p, f, 2.4022651e-1f);
    p = fmaf(p, f, 6.9314718e-1f);
    p = fmaf(p, f, 1.0f);
    int e = (int)t;
    return p * __int_as_float((e + 127) << 23);
}

// ---------------------------------------------------------------------------
// SGEMM: C[M,Ncols] = A[M,768] @ W[768,Ncols] + bias
// 64x128 CTA tile, 128 threads, 8x8 microtile, SPLIT B columns (conflict-free
// fragment loads). KB=32 split-staged prefetch, 24 syncs.
// Smem: 2*32*(64+128)*4 = 49152 B exactly (static limit).
// MODE 0: A = x, scatter into g_Q/g_K/g_V head-major. MODE 1: dense out.
// ---------------------------------------------------------------------------
#define KB     32
#define NCHUNK (HDIM / KB)      /* 24 */
#define ASTR   64

template<int MODE>
__global__ __launch_bounds__(128)
void sgemm_kernel(const float* __restrict__ A, const float* __restrict__ W,
                  const float* __restrict__ bias, float* __restrict__ out,
                  int Ncols)
{
    __shared__ float As[2][KB][ASTR];  // transposed [k][m]
    __shared__ float Bs[2][KB][128];   // natural [k][n]

    const int tid = threadIdx.x;
    const int m0  = blockIdx.y * 64;
    const int c0  = blockIdx.x * 128;
    const int ty  = tid >> 4;          // 0..7  -> rows ty*8..
    const int tx  = tid & 15;          // 0..15 -> col chunks tx*4 and 64+tx*4

    const float* Ap = (MODE == 0) ? A : g_AttO;

    // loaders: A = 4 float4 (one row, 32 k-cols), B = 8 float4 (rows br+4r)
    const int ar = tid >> 1;           // 0..63
    const int ac = (tid & 1) * 16;     // 0 or 16
    const int br = tid >> 5;           // 0..3
    const int bc = (tid & 31) * 4;     // 0..124

    float acc[8][8];
#pragma unroll
    for (int i = 0; i < 8; i++)
#pragma unroll
        for (int j = 0; j < 8; j++) acc[i][j] = 0.f;

    // ---- prologue: chunk 0 straight to smem buf 0 ----
    {
#pragma unroll
        for (int q = 0; q < 4; q++) {
            float4 av = *reinterpret_cast<const float4*>(
                Ap + (size_t)(m0 + ar) * HDIM + ac + q * 4);
            As[0][ac + q * 4 + 0][ar] = av.x;
            As[0][ac + q * 4 + 1][ar] = av.y;
            As[0][ac + q * 4 + 2][ar] = av.z;
            As[0][ac + q * 4 + 3][ar] = av.w;
        }
#pragma unroll
        for (int r = 0; r < 8; r++) {
            float4 bv = *reinterpret_cast<const float4*>(
                W + (size_t)(br + r * 4) * Ncols + c0 + bc);
            *reinterpret_cast<float4*>(&Bs[0][br + r * 4][bc]) = bv;
        }
    }
    __syncthreads();

    for (int ch = 0; ch < NCHUNK; ch++) {
        const int buf = ch & 1;
        const int nb  = buf ^ 1;
        const bool more = (ch + 1 < NCHUNK);
        const int kb = (ch + 1) * KB;

        // ---- phase 1 prefetch: A (4 f4) + B rows 0..12 (4 f4) ----
        float4 pa0, pa1, pa2, pa3, pb0, pb1, pb2, pb3;
        if (more) {
            pa0 = *reinterpret_cast<const float4*>(Ap + (size_t)(m0 + ar) * HDIM + kb + ac + 0);
            pa1 = *reinterpret_cast<const float4*>(Ap + (size_t)(m0 + ar) * HDIM + kb + ac + 4);
            pa2 = *reinterpret_cast<const float4*>(Ap + (size_t)(m0 + ar) * HDIM + kb + ac + 8);
            pa3 = *reinterpret_cast<const float4*>(Ap + (size_t)(m0 + ar) * HDIM + kb + ac + 12);
            pb0 = *reinterpret_cast<const float4*>(W + (size_t)(kb + br +  0) * Ncols + c0 + bc);
            pb1 = *reinterpret_cast<const float4*>(W + (size_t)(kb + br +  4) * Ncols + c0 + bc);
            pb2 = *reinterpret_cast<const float4*>(W + (size_t)(kb + br +  8) * Ncols + c0 + bc);
            pb3 = *reinterpret_cast<const float4*>(W + (size_t)(kb + br + 12) * Ncols + c0 + bc);
        }

#pragma unroll
        for (int k = 0; k < 16; k++) {
            float a[8], b[8];
            *(float4*)&a[0] = *(const float4*)&As[buf][k][ty * 8];
            *(float4*)&a[4] = *(const float4*)&As[buf][k][ty * 8 + 4];
            *(float4*)&b[0] = *(const float4*)&Bs[buf][k][tx * 4];
            *(float4*)&b[4] = *(const float4*)&Bs[buf][k][64 + tx * 4];
#pragma unroll
            for (int i = 0; i < 8; i++)
#pragma unroll
                for (int j = 0; j < 8; j++) acc[i][j] = fmaf(a[i], b[j], acc[i][j]);
        }

        // ---- mid-chunk: release phase-1 regs into idle buffer, fetch B hi ----
        float4 pb4, pb5, pb6, pb7;
        if (more) {
            As[nb][ac +  0][ar] = pa0.x; As[nb][ac +  1][ar] = pa0.y;
            As[nb][ac +  2][ar] = pa0.z; As[nb][ac +  3][ar] = pa0.w;
            As[nb][ac +  4][ar] = pa1.x; As[nb][ac +  5][ar] = pa1.y;
            As[nb][ac +  6][ar] = pa1.z; As[nb][ac +  7][ar] = pa1.w;
            As[nb][ac +  8][ar] = pa2.x; As[nb][ac +  9][ar] = pa2.y;
            As[nb][ac + 10][ar] = pa2.z; As[nb][ac + 11][ar] = pa2.w;
            As[nb][ac + 12][ar] = pa3.x; As[nb][ac + 13][ar] = pa3.y;
            As[nb][ac + 14][ar] = pa3.z; As[nb][ac + 15][ar] = pa3.w;
            *reinterpret_cast<float4*>(&Bs[nb][br +  0][bc]) = pb0;
            *reinterpret_cast<float4*>(&Bs[nb][br +  4][bc]) = pb1;
            *reinterpret_cast<float4*>(&Bs[nb][br +  8][bc]) = pb2;
            *reinterpret_cast<float4*>(&Bs[nb][br + 12][bc]) = pb3;
            pb4 = *reinterpret_cast<const float4*>(W + (size_t)(kb + br + 16) * Ncols + c0 + bc);
            pb5 = *reinterpret_cast<const float4*>(W + (size_t)(kb + br + 20) * Ncols + c0 + bc);
            pb6 = *reinterpret_cast<const float4*>(W + (size_t)(kb + br + 24) * Ncols + c0 + bc);
            pb7 = *reinterpret_cast<const float4*>(W + (size_t)(kb + br + 28) * Ncols + c0 + bc);
        }

#pragma unroll
        for (int k = 16; k < 32; k++) {
            float a[8], b[8];
            *(float4*)&a[0] = *(const float4*)&As[buf][k][ty * 8];
            *(float4*)&a[4] = *(const float4*)&As[buf][k][ty * 8 + 4];
            *(float4*)&b[0] = *(const float4*)&Bs[buf][k][tx * 4];
            *(float4*)&b[4] = *(const float4*)&Bs[buf][k][64 + tx * 4];
#pragma unroll
            for (int i = 0; i < 8; i++)
#pragma unroll
                for (int j = 0; j < 8; j++) acc[i][j] = fmaf(a[i], b[j], acc[i][j]);
        }

        if (more) {
            *reinterpret_cast<float4*>(&Bs[nb][br + 16][bc]) = pb4;
            *reinterpret_cast<float4*>(&Bs[nb][br + 20][bc]) = pb5;
            *reinterpret_cast<float4*>(&Bs[nb][br + 24][bc]) = pb6;
            *reinterpret_cast<float4*>(&Bs[nb][br + 28][bc]) = pb7;
        }
        __syncthreads();
    }

    // ---- epilogue: two 4-col chunks per row (round-15 verified) ----
    const int cb0 = c0 + tx * 4;
    const int cb1 = c0 + 64 + tx * 4;
    if (MODE == 0) {
        const int part = c0 / HDIM;
        float* dst = (part == 0) ? g_Q : (part == 1 ? g_K : g_V);
        const int cc0 = cb0 - part * HDIM, cc1 = cb1 - part * HDIM;
        const int h0 = cc0 >> 6, d0 = cc0 & 63;
        const int h1 = cc1 >> 6, d1 = cc1 & 63;
        const float4 bv0 = *reinterpret_cast<const float4*>(bias + cb0);
        const float4 bv1 = *reinterpret_cast<const float4*>(bias + cb1);
#pragma unroll
        for (int i = 0; i < 8; i++) {
            int m = m0 + ty * 8 + i;
            int bi = m >> 10, n = m & (SEQ - 1);
            float4 v0, v1;
            v0.x = acc[i][0] + bv0.x; v0.y = acc[i][1] + bv0.y;
            v0.z = acc[i][2] + bv0.z; v0.w = acc[i][3] + bv0.w;
            v1.x = acc[i][4] + bv1.x; v1.y = acc[i][5] + bv1.y;
            v1.z = acc[i][6] + bv1.z; v1.w = acc[i][7] + bv1.w;
            *reinterpret_cast<float4*>(
                dst + ((size_t)(bi * NHEADS + h0) * SEQ + n) * HD + d0) = v0;
            *reinterpret_cast<float4*>(
                dst + ((size_t)(bi * NHEADS + h1) * SEQ + n) * HD + d1) = v1;
        }
    } else {
        const float4 bv0 = *reinterpret_cast<const float4*>(bias + cb0);
        const float4 bv1 = *reinterpret_cast<const float4*>(bias + cb1);
#pragma unroll
        for (int i = 0; i < 8; i++) {
            int m = m0 + ty * 8 + i;
            float4 v0, v1;
            v0.x = acc[i][0] + bv0.x; v0.y = acc[i][1] + bv0.y;
            v0.z = acc[i][2] + bv0.z; v0.w = acc[i][3] + bv0.w;
            v1.x = acc[i][4] + bv1.x; v1.y = acc[i][5] + bv1.y;
            v1.z = acc[i][6] + bv1.z; v1.w = acc[i][7] + bv1.w;
            *reinterpret_cast<float4*>(out + (size_t)m * HDIM + cb0) = v0;
            *reinterpret_cast<float4*>(out + (size_t)m * HDIM + cb1) = v1;
        }
    }
}

// ---------------------------------------------------------------------------
// Flash attention (round-10/11 verified, FROZEN): 128 threads, 64x64 tile,
// 8x4 microtile, MUFU-free softmax, swizzled K/P staging.
// ---------------------------------------------------------------------------
__global__ __launch_bounds__(128)
void attn_kernel()
{
    __shared__ float Qs[64][64];
    __shared__ float Ks[64][64];
    __shared__ float Vs[64][64];

    const int tid = threadIdx.x;
    const int tx  = tid & 15;
    const int ty  = tid >> 4;
    const int b   = blockIdx.z, h = blockIdx.y;
    const int q0  = blockIdx.x * 64;

    const float* Qg = g_Q + (size_t)((b * NHEADS + h) * SEQ + q0) * HD;
    const float* Kg = g_K + (size_t)((b * NHEADS + h) * SEQ) * HD;
    const float* Vg = g_V + (size_t)((b * NHEADS + h) * SEQ) * HD;

    const float QSCALE = 0.125f * 1.4426950408889634f;
    float* ksf = &Ks[0][0];

    for (int f = tid; f < 1024; f += 128) {
        int r = f >> 4, c4 = (f & 15) << 2;
        float4 v = *reinterpret_cast<const float4*>(Qg + r * HD + c4);
        Qs[c4 + 0][r] = v.x * QSCALE; Qs[c4 + 1][r] = v.y * QSCALE;
        Qs[c4 + 2][r] = v.z * QSCALE; Qs[c4 + 3][r] = v.w * QSCALE;
    }

    float o[8][4], mrow[8], lrow[8];
#pragma unroll
    for (int i = 0; i < 8; i++) {
        mrow[i] = -1e30f; lrow[i] = 0.f;
#pragma unroll
        for (int j = 0; j < 4; j++) o[i][j] = 0.f;
    }

    for (int kt = 0; kt < SEQ / 64; kt++) {
        __syncthreads();
        const float* Kt = Kg + (size_t)kt * 64 * HD;
        const float* Vt = Vg + (size_t)kt * 64 * HD;
        for (int f = tid; f < 1024; f += 128) {
            int r  = f >> 4;
            int c4 = (f & 15) << 2;
            float4 kv = *reinterpret_cast<const float4*>(Kt + r * HD + c4);
            int sg   = ((r >> 2) + (c4 >> 2)) & 15;
            int base = sg * 4 + (r & 3);
            ksf[(c4 + 0) * 64 + base] = kv.x;
            ksf[(c4 + 1) * 64 + base] = kv.y;
            ksf[(c4 + 2) * 64 + base] = kv.z;
            ksf[(c4 + 3) * 64 + base] = kv.w;
            float4 vv = *reinterpret_cast<const float4*>(Vt + r * HD + c4);
            *reinterpret_cast<float4*>(&Vs[r][c4]) = vv;
        }
        __syncthreads();

        float s[8][4];
#pragma unroll
        for (int i = 0; i < 8; i++)
#pragma unroll
            for (int j = 0; j < 4; j++) s[i][j] = 0.f;
#pragma unroll 4
        for (int d = 0; d < 64; d++) {
            float qa[8], kb[4];
            *(float4*)&qa[0] = *(const float4*)&Qs[d][ty * 8];
            *(float4*)&qa[4] = *(const float4*)&Qs[d][ty * 8 + 4];
            int g = (tx + (d >> 2)) & 15;
            *(float4*)&kb[0] = *(const float4*)&ksf[d * 64 + g * 4];
#pragma unroll
            for (int i = 0; i < 8; i++)
#pragma unroll
                for (int j = 0; j < 4; j++) s[i][j] = fmaf(qa[i], kb[j], s[i][j]);
        }

#pragma unroll
        for (int i = 0; i < 8; i++) {
            float mx = fmaxf(fmaxf(s[i][0], s[i][1]), fmaxf(s[i][2], s[i][3]));
            mx = fmaxf(mx, __shfl_xor_sync(0xffffffffu, mx, 1));
            mx = fmaxf(mx, __shfl_xor_sync(0xffffffffu, mx, 2));
            mx = fmaxf(mx, __shfl_xor_sync(0xffffffffu, mx, 4));
            mx = fmaxf(mx, __shfl_xor_sync(0xffffffffu, mx, 8));
            float mnew = fmaxf(mrow[i], mx);
            float corr = exp2f_fast(mrow[i] - mnew);
            float rs = 0.f;
#pragma unroll
            for (int j = 0; j < 4; j++) {
                float p = exp2f_fast(s[i][j] - mnew);
                s[i][j] = p; rs += p;
            }
            rs += __shfl_xor_sync(0xffffffffu, rs, 1);
            rs += __shfl_xor_sync(0xffffffffu, rs, 2);
            rs += __shfl_xor_sync(0xffffffffu, rs, 4);
            rs += __shfl_xor_sync(0xffffffffu, rs, 8);
            lrow[i] = lrow[i] * corr + rs;
            mrow[i] = mnew;
#pragma unroll
            for (int j = 0; j < 4; j++) o[i][j] *= corr;
        }

        __syncthreads();
#pragma unroll
        for (int j = 0; j < 4; j++) {
            const int kv = tx * 4 + j;
            const int g0 = ((2 * ty)     + tx) & 15;
            const int g1 = ((2 * ty + 1) + tx) & 15;
            float4 p0, p1;
            p0.x = s[0][j]; p0.y = s[1][j]; p0.z = s[2][j]; p0.w = s[3][j];
            p1.x = s[4][j]; p1.y = s[5][j]; p1.z = s[6][j]; p1.w = s[7][j];
            *reinterpret_cast<float4*>(&ksf[kv * 64 + g0 * 4]) = p0;
            *reinterpret_cast<float4*>(&ksf[kv * 64 + g1 * 4]) = p1;
        }
        __syncthreads();

#pragma unroll 4
        for (int k = 0; k < 64; k++) {
            float pa[8], vb[4];
            const int g0 = ((2 * ty)     + (k >> 2)) & 15;
            const int g1 = ((2 * ty + 1) + (k >> 2)) & 15;
            *(float4*)&pa[0] = *(const float4*)&ksf[k * 64 + g0 * 4];
            *(float4*)&pa[4] = *(const float4*)&ksf[k * 64 + g1 * 4];
            *(float4*)&vb[0] = *(const float4*)&Vs[k][tx * 4];
#pragma unroll
            for (int i = 0; i < 8; i++)
#pragma unroll
                for (int j = 0; j < 4; j++) o[i][j] = fmaf(pa[i], vb[j], o[i][j]);
        }
    }

#pragma unroll
    for (int i = 0; i < 8; i++) {
        float inv = 1.f / lrow[i];
        int n = q0 + ty * 8 + i;
        float4 v;
        v.x = o[i][0] * inv; v.y = o[i][1] * inv;
        v.z = o[i][2] * inv; v.w = o[i][3] * inv;
        *reinterpret_cast<float4*>(
            g_AttO + (size_t)(b * SEQ + n) * HDIM + h * HD + tx * 4) = v;
    }
}

// ---------------------------------------------------------------------------
extern "C" void kernel_launch(void* const* d_in, const int* in_sizes, int n_in,
                              void* d_out, int out_size)
{
    const float* x     = (const float*)d_in[0];
    const float* w_qkv = (const float*)d_in[1];
    const float* b_qkv = (const float*)d_in[2];
    const float* w_out = (const float*)d_in[3];
    const float* b_out = (const float*)d_in[4];
    float* out = (float*)d_out;
    (void)in_sizes; (void)n_in; (void)out_size;

    dim3 g1(QKVN / 128, MTOK / 64);                  // 18 x 256 blocks
    sgemm_kernel<0><<<g1, 128>>>(x, w_qkv, b_qkv, nullptr, QKVN);

    dim3 g2(SEQ / 64, NHEADS, BATCH);                // 16 x 12 x 16 blocks
    attn_kernel<<<g2, 128>>>();

    dim3 g3(HDIM / 128, MTOK / 64);                  // 6 x 256 blocks
    sgemm_kernel<1><<<g3, 128>>>(g_AttO, w_out, b_out, out, HDIM);
}